// round 7
// baseline (speedup 1.0000x reference)
#include <cuda_runtime.h>

// LSEP loss: log1p( sum_i [ exp(-x[i,y_i]) * sum_j exp(x[i,j]) ] - B )
//
// Key change vs prior rounds: NO pos gather from gmem. The warp already holds
// the full row in registers, so x[row, y] is extracted with selects + one
// __shfl_sync (owner lane = (y>>2)&31, buffer = (y>>2)/32, component = y&3).
// This removes the second (random-sector) address stream, the tgt->pos
// dependency chain, and its prefetch registers. Two adjacent rows per warp
// iteration (6 front-batched LDG.128 = contiguous 2720B). Lane-partial trick:
// each lane scales its own partial row sum by exp(-pos); per-row -1 folded
// into a single -B. Fused last-block-done reduce (self-resetting counter ->
// graph-replay safe, deterministic order).

#define NCLS   340
#define NCLS4  85            // 340/4; row stride 1360 B is 16B-aligned
#define GRID   888           // 148 SMs * 6 CTAs (regs ~40)
#define BLOCK  256
#define WPB    (BLOCK / 32)

__device__ double       g_partials[GRID];
__device__ unsigned int g_count = 0;     // wraps via atomicInc -> replay-safe

__device__ __forceinline__ float exp4(float4 v) {
    return __expf(v.x) + __expf(v.y) + __expf(v.z) + __expf(v.w);
}

// Extract x[row, y] from the warp's row-resident registers.
// v0 holds cols [4*lane, 4*lane+3], v1 cols [4*(lane+32)..], v2 cols [4*(lane+64)..]
__device__ __forceinline__ float row_extract(float4 v0, float4 v1, float4 v2, int y) {
    const int q = y >> 2;          // float4 index 0..84 (uniform across warp)
    const int r = y & 3;
    float4 v = (q < 32) ? v0 : (q < 64) ? v1 : v2;
    float c = (r == 0) ? v.x : (r == 1) ? v.y : (r == 2) ? v.z : v.w;
    return __shfl_sync(0xffffffffu, c, q & 31);
}

__global__ __launch_bounds__(BLOCK)
void lsep_kernel(const float* __restrict__ x,
                 const int*   __restrict__ tgt,
                 float*       __restrict__ out,
                 int B)
{
    const int lane   = threadIdx.x & 31;
    const int warp   = threadIdx.x >> 5;
    const int wglob  = blockIdx.x * WPB + warp;
    const int wtotal = GRID * WPB;

    const bool tail = lane < (NCLS4 - 64);   // lanes 0..20 own the 3rd float4
    const int  nPairs = B >> 1;
    const int2* __restrict__ t2 = (const int2*)tgt;

    double acc = 0.0;

    for (int p = wglob; p < nPairs; p += wtotal) {
        const float* xA = x + (size_t)(p * 2) * NCLS;
        const float4* rA = (const float4*)xA;
        const float4* rB = (const float4*)(xA + NCLS);

        int2 y = t2[p];
        y.x = min(max(y.x, 0), NCLS - 1);
        y.y = min(max(y.y, 0), NCLS - 1);

        // 6 front-batched LDG.128 (contiguous 2720 B)
        float4 a0 = rA[lane], a1 = rA[lane + 32];
        float4 b0 = rB[lane], b1 = rB[lane + 32];
        float4 a2 = a0, b2 = b0;
        if (tail) { a2 = rA[lane + 64]; b2 = rB[lane + 64]; }

        float sA = exp4(a0) + exp4(a1);
        float sB = exp4(b0) + exp4(b1);
        if (tail) { sA += exp4(a2); sB += exp4(b2); }

        const float posA = row_extract(a0, a1, a2, y.x);
        const float posB = row_extract(b0, b1, b2, y.y);

        acc += (double)(sA * __expf(-posA))
             + (double)(sB * __expf(-posB));
    }

    // ---- block reduction (deterministic) ----
    #pragma unroll
    for (int o = 16; o; o >>= 1)
        acc += __shfl_xor_sync(0xffffffffu, acc, o);

    __shared__ double sacc[WPB];
    __shared__ bool   is_last;
    if (lane == 0) sacc[warp] = acc;
    __syncthreads();

    if (threadIdx.x == 0) {
        double t = 0.0;
        #pragma unroll
        for (int i = 0; i < WPB; i++) t += sacc[i];
        g_partials[blockIdx.x] = t;
        __threadfence();
        unsigned int old = atomicInc(&g_count, GRID - 1);   // wraps to 0
        is_last = (old == GRID - 1);
    }
    __syncthreads();

    // ---- last block: deterministic final reduce + log1p ----
    if (is_last) {
        __threadfence();
        __shared__ double sfin[BLOCK];
        double t = 0.0;
        for (int i = threadIdx.x; i < GRID; i += BLOCK)
            t += g_partials[i];
        sfin[threadIdx.x] = t;
        __syncthreads();
        #pragma unroll
        for (int o = BLOCK / 2; o; o >>= 1) {
            if (threadIdx.x < o) sfin[threadIdx.x] += sfin[threadIdx.x + o];
            __syncthreads();
        }
        if (threadIdx.x == 0)
            out[0] = (float)log1p(sfin[0] - (double)B);
    }
}

extern "C" void kernel_launch(void* const* d_in, const int* in_sizes, int n_in,
                              void* d_out, int out_size)
{
    const float* x   = (const float*)d_in[0];
    const int*   tgt = (const int*)d_in[1];
    float*       out = (float*)d_out;

    int B = in_sizes[0] / NCLS;   // 65536

    lsep_kernel<<<GRID, BLOCK>>>(x, tgt, out, B);
}

// round 8
// speedup vs baseline: 1.0399x; 1.0399x over previous
#include <cuda_runtime.h>

// LSEP loss: log1p( sum_i [ exp(-x[i,y_i]) * sum_j exp(x[i,j]) ] - B )
//
// R6 register double-buffered pipeline at FULL occupancy (GRID=888 = 6 CTAs/SM
// at 40 regs; R6 was grid-capped to 4). While a warp computes row i's exps,
// row i+1's three float4 loads + its pos gather are in flight; tgt prefetched
// two iterations ahead so y->pos never serializes. Lane-partial trick (each
// lane scales its own partial row sum by exp(-pos)); per-row -1 folded into
// -B. Fused last-block-done reduce (self-resetting counter -> graph-replay
// safe, deterministic order).

#define NCLS   340
#define NCLS4  85            // 340/4; row stride 1360 B is 16B-aligned
#define GRID   888           // 148 SMs * 6 CTAs
#define BLOCK  256
#define WPB    (BLOCK / 32)

__device__ double       g_partials[GRID];
__device__ unsigned int g_count = 0;     // wraps via atomicInc -> replay-safe

__device__ __forceinline__ float exp4(float4 v) {
    return __expf(v.x) + __expf(v.y) + __expf(v.z) + __expf(v.w);
}

__global__ __launch_bounds__(BLOCK)
void lsep_pipe_kernel(const float* __restrict__ x,
                      const int*   __restrict__ tgt,
                      float*       __restrict__ out,
                      int B)
{
    const int lane   = threadIdx.x & 31;
    const int warp   = threadIdx.x >> 5;
    const int wglob  = blockIdx.x * WPB + warp;
    const int wtotal = GRID * WPB;

    const bool tail = lane < (NCLS4 - 64);   // lanes 0..20 own the 3rd float4

    double acc = 0.0;

    int row = wglob;
    if (row < B) {
        // ---- prologue: fill the pipeline ----
        const float4* rc = (const float4*)(x + (size_t)row * NCLS);
        float4 c0 = rc[lane];
        float4 c1 = rc[lane + 32];
        float4 c2 = c0;
        if (tail) c2 = rc[lane + 64];

        int yc = tgt[row];
        yc = min(max(yc, 0), NCLS - 1);
        float posc = __ldg(x + (size_t)row * NCLS + yc);

        int r1 = row + wtotal;
        int yn = 0;
        if (r1 < B) {
            yn = tgt[r1];
            yn = min(max(yn, 0), NCLS - 1);
        }

        for (;;) {
            const int rn1 = row + wtotal;          // next row (data+pos)
            const int rn2 = row + 2 * wtotal;      // next-next (target only)
            const bool more = rn1 < B;

            float4 n0, n1, n2;
            float  posn = 0.0f;
            if (more) {
                const float4* rn = (const float4*)(x + (size_t)rn1 * NCLS);
                n0 = rn[lane];
                n1 = rn[lane + 32];
                n2 = n0;
                if (tail) n2 = rn[lane + 64];
                posn = __ldg(x + (size_t)rn1 * NCLS + yn);   // yn resident
            }
            int yn2 = 0;
            if (rn2 < B) {
                yn2 = tgt[rn2];
                yn2 = min(max(yn2, 0), NCLS - 1);
            }

            // ---- compute current row while next row's loads fly ----
            float s = exp4(c0) + exp4(c1);
            if (tail) s += exp4(c2);
            acc += (double)(s * __expf(-posc));

            if (!more) break;
            c0 = n0; c1 = n1; c2 = n2;
            posc = posn; yn = yn2;
            row = rn1;
        }
    }

    // ---- block reduction (deterministic) ----
    #pragma unroll
    for (int o = 16; o; o >>= 1)
        acc += __shfl_xor_sync(0xffffffffu, acc, o);

    __shared__ double sacc[WPB];
    __shared__ bool   is_last;
    if (lane == 0) sacc[warp] = acc;
    __syncthreads();

    if (threadIdx.x == 0) {
        double t = 0.0;
        #pragma unroll
        for (int i = 0; i < WPB; i++) t += sacc[i];
        g_partials[blockIdx.x] = t;
        __threadfence();
        unsigned int old = atomicInc(&g_count, GRID - 1);   // wraps to 0
        is_last = (old == GRID - 1);
    }
    __syncthreads();

    // ---- last block: deterministic final reduce + log1p ----
    if (is_last) {
        __threadfence();
        __shared__ double sfin[BLOCK];
        double t = 0.0;
        for (int i = threadIdx.x; i < GRID; i += BLOCK)
            t += g_partials[i];
        sfin[threadIdx.x] = t;
        __syncthreads();
        #pragma unroll
        for (int o = BLOCK / 2; o; o >>= 1) {
            if (threadIdx.x < o) sfin[threadIdx.x] += sfin[threadIdx.x + o];
            __syncthreads();
        }
        if (threadIdx.x == 0)
            out[0] = (float)log1p(sfin[0] - (double)B);
    }
}

extern "C" void kernel_launch(void* const* d_in, const int* in_sizes, int n_in,
                              void* d_out, int out_size)
{
    const float* x   = (const float*)d_in[0];
    const int*   tgt = (const int*)d_in[1];
    float*       out = (float*)d_out;

    int B = in_sizes[0] / NCLS;   // 65536

    lsep_pipe_kernel<<<GRID, BLOCK>>>(x, tgt, out, B);
}

// round 9
// speedup vs baseline: 1.2792x; 1.2301x over previous
#include <cuda_runtime.h>

// LSEP loss: log1p( sum_i [ exp(-x[i,y_i]) * sum_j exp(x[i,j]) ] - B )
//
// R6 register-pipelined kernel with the FP64 accumulator REMOVED from the hot
// loop: fp64 DADD/F2F cost ~18.4 cyc/SM each on B300 and dominated the per-row
// issue budget (~37 of ~105 cyc/row). Each warp handles only ~10 rows, so a
// per-lane float accumulator adds <1e-6 rel error; converted to double once
// after the loop. Cross-warp/block reduction unchanged (fp64, deterministic).
// While a warp computes row i's exps, row i+1's loads + pos gather are in
// flight; tgt prefetched two ahead. Lane-partial trick; per-row -1 folded
// into -B. Fused last-block-done reduce (self-resetting counter).

#define NCLS   340
#define NCLS4  85            // 340/4; row stride 1360 B is 16B-aligned
#define GRID   592           // best-known config (R6)
#define BLOCK  256
#define WPB    (BLOCK / 32)

__device__ double       g_partials[GRID];
__device__ unsigned int g_count = 0;     // wraps via atomicInc -> replay-safe

__device__ __forceinline__ float exp4(float4 v) {
    return __expf(v.x) + __expf(v.y) + __expf(v.z) + __expf(v.w);
}

__global__ __launch_bounds__(BLOCK)
void lsep_pipe_kernel(const float* __restrict__ x,
                      const int*   __restrict__ tgt,
                      float*       __restrict__ out,
                      int B)
{
    const int lane   = threadIdx.x & 31;
    const int warp   = threadIdx.x >> 5;
    const int wglob  = blockIdx.x * WPB + warp;
    const int wtotal = GRID * WPB;

    const bool tail = lane < (NCLS4 - 64);   // lanes 0..20 own the 3rd float4

    float accf = 0.0f;                       // fp32 in the hot loop (~10 adds)

    int row = wglob;
    if (row < B) {
        // ---- prologue: fill the pipeline ----
        const float4* rc = (const float4*)(x + (size_t)row * NCLS);
        float4 c0 = rc[lane];
        float4 c1 = rc[lane + 32];
        float4 c2 = c0;
        if (tail) c2 = rc[lane + 64];

        int yc = tgt[row];
        yc = min(max(yc, 0), NCLS - 1);
        float posc = __ldg(x + (size_t)row * NCLS + yc);

        int r1 = row + wtotal;
        int yn = 0;
        if (r1 < B) {
            yn = tgt[r1];
            yn = min(max(yn, 0), NCLS - 1);
        }

        for (;;) {
            const int rn1 = row + wtotal;          // next row (data+pos)
            const int rn2 = row + 2 * wtotal;      // next-next (target only)
            const bool more = rn1 < B;

            float4 n0, n1, n2;
            float  posn = 0.0f;
            if (more) {
                const float4* rn = (const float4*)(x + (size_t)rn1 * NCLS);
                n0 = rn[lane];
                n1 = rn[lane + 32];
                n2 = n0;
                if (tail) n2 = rn[lane + 64];
                posn = __ldg(x + (size_t)rn1 * NCLS + yn);   // yn resident
            }
            int yn2 = 0;
            if (rn2 < B) {
                yn2 = tgt[rn2];
                yn2 = min(max(yn2, 0), NCLS - 1);
            }

            // ---- compute current row while next row's loads fly ----
            float s = exp4(c0) + exp4(c1);
            if (tail) s += exp4(c2);
            accf += s * __expf(-posc);             // fp32: no DADD in loop

            if (!more) break;
            c0 = n0; c1 = n1; c2 = n2;
            posc = posn; yn = yn2;
            row = rn1;
        }
    }

    double acc = (double)accf;                     // one convert per warp

    // ---- block reduction (deterministic) ----
    #pragma unroll
    for (int o = 16; o; o >>= 1)
        acc += __shfl_xor_sync(0xffffffffu, acc, o);

    __shared__ double sacc[WPB];
    __shared__ bool   is_last;
    if (lane == 0) sacc[warp] = acc;
    __syncthreads();

    if (threadIdx.x == 0) {
        double t = 0.0;
        #pragma unroll
        for (int i = 0; i < WPB; i++) t += sacc[i];
        g_partials[blockIdx.x] = t;
        __threadfence();
        unsigned int old = atomicInc(&g_count, GRID - 1);   // wraps to 0
        is_last = (old == GRID - 1);
    }
    __syncthreads();

    // ---- last block: deterministic final reduce + log1p ----
    if (is_last) {
        __threadfence();
        __shared__ double sfin[BLOCK];
        double t = 0.0;
        for (int i = threadIdx.x; i < GRID; i += BLOCK)
            t += g_partials[i];
        sfin[threadIdx.x] = t;
        __syncthreads();
        #pragma unroll
        for (int o = BLOCK / 2; o; o >>= 1) {
            if (threadIdx.x < o) sfin[threadIdx.x] += sfin[threadIdx.x + o];
            __syncthreads();
        }
        if (threadIdx.x == 0)
            out[0] = (float)log1p(sfin[0] - (double)B);
    }
}

extern "C" void kernel_launch(void* const* d_in, const int* in_sizes, int n_in,
                              void* d_out, int out_size)
{
    const float* x   = (const float*)d_in[0];
    const int*   tgt = (const int*)d_in[1];
    float*       out = (float*)d_out;

    int B = in_sizes[0] / NCLS;   // 65536

    lsep_pipe_kernel<<<GRID, BLOCK>>>(x, tgt, out, B);
}